// round 13
// baseline (speedup 1.0000x reference)
#include <cuda_runtime.h>
#include <cuda_bf16.h>
#include <cstdint>
#include <math.h>

// Problem constants
#define NB 16
#define NC 512
#define NS 128
#define NT 2048
#define PADW 18    // W_LEN/2, W_LEN=37
#define TSTR 2050  // padded t rows for transposed conv input (1 zero row each end)

// ---------------------------------------------------------------------------
// Device scratch (no allocation allowed; zero-initialized at module load,
// pad rows of g_T* are never written so they stay zero -> implicit conv pad)
// ---------------------------------------------------------------------------
__device__ float g_ws[NB * NS * NT];                                   // win_sum(s)
__device__ float g_y2[(size_t)NB * NC * NT];                           // conv1 fp32 out
__device__ __align__(16) __nv_bfloat16 g_Thi[(size_t)NB * TSTR * NC];  // conv in, transposed, hi
__device__ __align__(16) __nv_bfloat16 g_Tlo[(size_t)NB * TSTR * NC];  // conv in, transposed, lo
__device__ __align__(16) __nv_bfloat16 g_wA[(size_t)2 * 6 * NC * NC];  // weights [conv][tap*2+spl][co][ci]

// ---------------------------------------------------------------------------
// mma.sync m16n8k16 bf16 (row.col), fp32 accumulate — sm_80+ baseline feature
// ---------------------------------------------------------------------------
__device__ __forceinline__ void mma16816(float* c, const uint32_t* a, const uint32_t* b) {
    asm volatile(
        "mma.sync.aligned.m16n8k16.row.col.f32.bf16.bf16.f32 "
        "{%0,%1,%2,%3}, {%4,%5,%6,%7}, {%8,%9}, {%0,%1,%2,%3};"
        : "+f"(c[0]), "+f"(c[1]), "+f"(c[2]), "+f"(c[3])
        : "r"(a[0]), "r"(a[1]), "r"(a[2]), "r"(a[3]), "r"(b[0]), "r"(b[1]));
}

// ---------------------------------------------------------------------------
// Kernel 1: sliding window sum of s over t (window 37)
// ---------------------------------------------------------------------------
__global__ void __launch_bounds__(256) winsum_s_kernel(const float* __restrict__ s) {
    __shared__ float sm[NT + 2 * PADW];
    const int row = blockIdx.x;
    const float* src = s + (size_t)row * NT;
    const int tid = threadIdx.x;
    for (int t = tid; t < NT; t += 256) sm[PADW + t] = src[t];
    if (tid < PADW) { sm[tid] = 0.0f; sm[PADW + NT + tid] = 0.0f; }
    __syncthreads();

    const int t0 = tid * 8;
    float sum = 0.0f;
#pragma unroll
    for (int k = 0; k < 37; k++) sum += sm[t0 + k];
    float* dst = g_ws + (size_t)row * NT + t0;
    dst[0] = sum;
#pragma unroll
    for (int j = 1; j < 8; j++) {
        sum += sm[t0 + j + 36] - sm[t0 + j - 1];
        dst[j] = sum;
    }
}

// ---------------------------------------------------------------------------
// Kernel 1b: split + rearrange conv weights -> g_wA[conv][tap*2+spl][co][ci] bf16
// ---------------------------------------------------------------------------
__global__ void __launch_bounds__(256) wprep_kernel(const float* __restrict__ w1,
                                                    const float* __restrict__ w2) {
    const int idx = blockIdx.x * 256 + threadIdx.x;   // over 2*512*512
    const int conv = idx >> 18;
    const int rem = idx & 262143;
    const int co = rem >> 9, ci = rem & 511;
    const float* w = conv ? w2 : w1;
#pragma unroll
    for (int tap = 0; tap < 3; tap++) {
        const float v = w[(co * NC + ci) * 3 + tap];
        const __nv_bfloat16 h = __float2bfloat16(v);
        const __nv_bfloat16 l = __float2bfloat16(v - __bfloat162float(h));
        g_wA[((size_t)(conv * 6 + tap * 2 + 0) * NC + co) * NC + ci] = h;
        g_wA[((size_t)(conv * 6 + tap * 2 + 1) * NC + co) * NC + ci] = l;
    }
}

// ---------------------------------------------------------------------------
// Kernel 2: fused adawin stage (fp32 FFMA GEMM K=128 + epilogue).
// Epilogue emits leaky_relu result directly as TRANSPOSED bf16 hi/lo arrays
// g_T*[b][t+1][c] (conv input; taps become row offsets; pad rows stay zero).
// ---------------------------------------------------------------------------
template<bool STAGE2>
__global__ void __launch_bounds__(256) adawin_kernel(
    const float* __restrict__ fc_w, const float* __restrict__ fc_b,
    const float* __restrict__ alpha, const float* __restrict__ xin_p,
    const int* __restrict__ lengths)
{
    const int b  = blockIdx.z;
    const int c0 = blockIdx.y * 64;
    const int t0 = blockIdx.x * 64;
    const int tid = threadIdx.x;
    const int tx = tid & 15, ty = tid >> 4;

    __shared__ float Ag[16 * 68];
    __shared__ float Ab[16 * 68];
    __shared__ float Bs[16 * 68];

    float accg[4][4] = {};
    float accb[4][4] = {};

    const float* wsb = g_ws + (size_t)b * NS * NT;

    for (int k0 = 0; k0 < NS; k0 += 16) {
#pragma unroll
        for (int n = tid; n < 1024; n += 256) {
            const int kk = n & 15, i = n >> 4;
            Ag[kk * 68 + i] = fc_w[(c0 + i) * NS + k0 + kk];
            Ab[kk * 68 + i] = fc_w[(c0 + 512 + i) * NS + k0 + kk];
        }
#pragma unroll
        for (int n = tid; n < 1024; n += 256) {
            const int kk = n >> 6, j = n & 63;
            Bs[kk * 68 + j] = wsb[(k0 + kk) * NT + t0 + j];
        }
        __syncthreads();
#pragma unroll
        for (int kk = 0; kk < 16; kk++) {
            const float4 ag4 = *(const float4*)&Ag[kk * 68 + ty * 4];
            const float4 ab4 = *(const float4*)&Ab[kk * 68 + ty * 4];
            const float4 bv4 = *(const float4*)&Bs[kk * 68 + tx * 4];
            const float ag[4] = {ag4.x, ag4.y, ag4.z, ag4.w};
            const float ab[4] = {ab4.x, ab4.y, ab4.z, ab4.w};
            const float bv[4] = {bv4.x, bv4.y, bv4.z, bv4.w};
#pragma unroll
            for (int i = 0; i < 4; i++)
#pragma unroll
                for (int j = 0; j < 4; j++) {
                    accg[i][j] += ag[i] * bv[j];
                    accb[i][j] += ab[i] * bv[j];
                }
        }
        __syncthreads();
    }

    const int len = lengths[b];
    const float al = alpha[0];
    const float* xin = STAGE2 ? (const float*)g_y2 : xin_p;

    float vv[4][4];
#pragma unroll
    for (int i = 0; i < 4; i++) {
        const int c = c0 + ty * 4 + i;
        const float bg = fc_b[c];
        const float bb = fc_b[c + 512];
        const size_t rowoff = ((size_t)b * NC + c) * NT;
#pragma unroll
        for (int j = 0; j < 4; j++) {
            const int t = t0 + tx * 4 + j;
            const int lo = max(t - PADW, 0);
            const int hi = min(t + PADW, NT - 1);
            const float nwin = (float)(hi - lo + 1);
            int cnt = min(hi, len - 1) - lo + 1;
            cnt = max(cnt, 0);
            const float denom = (float)cnt + 1e-9f;
            const float m = (t < len) ? 1.0f : 0.0f;
            const float gam = (accg[i][j] + bg * nwin) / denom * m;
            const float bet = (accb[i][j] + bb * nwin) / denom * m;
            const float xn = tanhf(al * xin[rowoff + t]);
            float v = (1.0f + gam) * xn + bet;
            vv[i][j] = (v > 0.0f) ? v : 0.2f * v;   // leaky_relu 0.2
        }
    }

    // transposed bf16 hi/lo stores (4 c contiguous -> 8B packed stores)
#pragma unroll
    for (int j = 0; j < 4; j++) {
        const int t = t0 + tx * 4 + j;
        uint32_t hsh[2], hsl[2];
#pragma unroll
        for (int p = 0; p < 2; p++) {
            uint32_t h0, h1, l0, l1;
            {
                const float v = vv[p * 2 + 0][j];
                const __nv_bfloat16 h = __float2bfloat16(v);
                h0 = (uint32_t)__bfloat16_as_ushort(h);
                l0 = (uint32_t)__bfloat16_as_ushort(__float2bfloat16(v - __bfloat162float(h)));
            }
            {
                const float v = vv[p * 2 + 1][j];
                const __nv_bfloat16 h = __float2bfloat16(v);
                h1 = (uint32_t)__bfloat16_as_ushort(h);
                l1 = (uint32_t)__bfloat16_as_ushort(__float2bfloat16(v - __bfloat162float(h)));
            }
            hsh[p] = h0 | (h1 << 16);
            hsl[p] = l0 | (l1 << 16);
        }
        const size_t off = ((size_t)b * TSTR + t + 1) * NC + c0 + ty * 4;
        *(uint2*)&g_Thi[off] = make_uint2(hsh[0], hsh[1]);
        *(uint2*)&g_Tlo[off] = make_uint2(hsl[0], hsl[1]);
    }
}

// ---------------------------------------------------------------------------
// Kernel 3: conv1d k=3 via mma.sync bf16 (hi/lo 3-product split).
// CTA tile: M=128(co) x N=128(t); 8 warps (4m x 2n), warp tile 32x64.
// K loop: 16 chunks of 32 ci; per chunk all 3 taps x 3 products accumulate.
// A SMEM: [tap*2+spl][128 co][32 ci] stride 40 bf16 (80B rows).
// B SMEM: [spl][130 t rows][32 ci]  stride 40 bf16; tap = row offset.
// ---------------------------------------------------------------------------
#define CV_ASTRIDE 80                       // bytes per 32-ci row (40 bf16)
#define CV_ATILE   (128 * CV_ASTRIDE)       // 10240 B per (tap,spl) tile
#define CV_B_OFF   (6 * CV_ATILE)           // 61440
#define CV_BTILE   (130 * CV_ASTRIDE)       // 10400 B per spl
#define CV_SMEM_TOTAL (CV_B_OFF + 2 * CV_BTILE)  // 82240

template<bool FINAL>
__global__ void __launch_bounds__(256) conv_mma_kernel(
    int conv_sel, const float* __restrict__ bias,
    const float* __restrict__ xres, float* __restrict__ outp)
{
    extern __shared__ char smem[];
    const int tid = threadIdx.x;
    const int lane = tid & 31, wid = tid >> 5;
    const int wm = (wid & 3) * 32;        // warp m offset (co)
    const int wn = (wid >> 2) * 64;       // warp n offset (t)
    const int g = lane >> 2, q = lane & 3;

    const int b   = blockIdx.z;
    const int co0 = blockIdx.y * 128;
    const int tg0 = blockIdx.x * 128;

    const __nv_bfloat16* wA = g_wA + (size_t)conv_sel * 6 * NC * NC;
    const size_t tbase = (size_t)b * TSTR * NC;

    float acc[2][8][4] = {};

    for (int chunk = 0; chunk < 16; chunk++) {
        const int k0 = chunk * 32;
        __syncthreads();
        // ---- fill A: 6 tiles x 128 rows x 32 ci = 3072 uint4 ----
#pragma unroll
        for (int n = tid; n < 3072; n += 256) {
            const int ts = n >> 9, rem = n & 511;
            const int row = rem >> 2, c8 = rem & 3;
            const uint4 v = *(const uint4*)&wA[((size_t)ts * NC + co0 + row) * NC + k0 + c8 * 8];
            *(uint4*)(smem + ts * CV_ATILE + row * CV_ASTRIDE + c8 * 16) = v;
        }
        // ---- fill B: 2 spl x 130 rows x 32 ci = 1040 uint4 ----
        for (int n = tid; n < 1040; n += 256) {
            const int spl = n / 520, rem = n % 520;
            const int row = rem >> 2, c8 = rem & 3;
            const __nv_bfloat16* src = spl ? g_Tlo : g_Thi;
            const uint4 v = *(const uint4*)&src[tbase + (size_t)(tg0 + row) * NC + k0 + c8 * 8];
            *(uint4*)(smem + CV_B_OFF + spl * CV_BTILE + row * CV_ASTRIDE + c8 * 16) = v;
        }
        __syncthreads();

#pragma unroll
        for (int tap = 0; tap < 3; tap++) {
#pragma unroll
            for (int k16 = 0; k16 < 2; k16++) {
                const int kb = (k16 * 16 + q * 2) * 2;   // byte offset in k dim
                uint32_t ah[2][4], al[2][4], bh[8][2], bl[8][2];
                const char* Ah = smem + (tap * 2 + 0) * CV_ATILE;
                const char* Al = smem + (tap * 2 + 1) * CV_ATILE;
#pragma unroll
                for (int mi = 0; mi < 2; mi++) {
                    const int r = (wm + mi * 16 + g) * CV_ASTRIDE + kb;
                    ah[mi][0] = *(const uint32_t*)(Ah + r);
                    ah[mi][1] = *(const uint32_t*)(Ah + r + 8 * CV_ASTRIDE);
                    ah[mi][2] = *(const uint32_t*)(Ah + r + 16);
                    ah[mi][3] = *(const uint32_t*)(Ah + r + 8 * CV_ASTRIDE + 16);
                    al[mi][0] = *(const uint32_t*)(Al + r);
                    al[mi][1] = *(const uint32_t*)(Al + r + 8 * CV_ASTRIDE);
                    al[mi][2] = *(const uint32_t*)(Al + r + 16);
                    al[mi][3] = *(const uint32_t*)(Al + r + 8 * CV_ASTRIDE + 16);
                }
                const char* Bh = smem + CV_B_OFF + tap * CV_ASTRIDE;
                const char* Bl = smem + CV_B_OFF + CV_BTILE + tap * CV_ASTRIDE;
#pragma unroll
                for (int nj = 0; nj < 8; nj++) {
                    const int r = (wn + nj * 8 + g) * CV_ASTRIDE + kb;
                    bh[nj][0] = *(const uint32_t*)(Bh + r);
                    bh[nj][1] = *(const uint32_t*)(Bh + r + 16);
                    bl[nj][0] = *(const uint32_t*)(Bl + r);
                    bl[nj][1] = *(const uint32_t*)(Bl + r + 16);
                }
#pragma unroll
                for (int mi = 0; mi < 2; mi++)
#pragma unroll
                    for (int nj = 0; nj < 8; nj++) {
                        mma16816(acc[mi][nj], ah[mi], bh[nj]);   // hi*hi
                        mma16816(acc[mi][nj], ah[mi], bl[nj]);   // hi*lo
                        mma16816(acc[mi][nj], al[mi], bh[nj]);   // lo*hi
                    }
            }
        }
    }

    // ---- epilogue ----
    const float inv = 0.70710678118654752f;
#pragma unroll
    for (int mi = 0; mi < 2; mi++) {
        const int co_a = co0 + wm + mi * 16 + g;
        const int co_b = co_a + 8;
        const float bva = bias[co_a];
        const float bvb = bias[co_b];
        const size_t ra = ((size_t)b * NC + co_a) * NT;
        const size_t rb = ((size_t)b * NC + co_b) * NT;
#pragma unroll
        for (int nj = 0; nj < 8; nj++) {
            const int t = tg0 + wn + nj * 8 + q * 2;
            float2 va = make_float2(acc[mi][nj][0] + bva, acc[mi][nj][1] + bva);
            float2 vb = make_float2(acc[mi][nj][2] + bvb, acc[mi][nj][3] + bvb);
            if (FINAL) {
                const float2 xa = *(const float2*)&xres[ra + t];
                const float2 xb = *(const float2*)&xres[rb + t];
                va.x = (va.x + xa.x) * inv; va.y = (va.y + xa.y) * inv;
                vb.x = (vb.x + xb.x) * inv; vb.y = (vb.y + xb.y) * inv;
                *(float2*)&outp[ra + t] = va;
                *(float2*)&outp[rb + t] = vb;
            } else {
                *(float2*)&g_y2[ra + t] = va;
                *(float2*)&g_y2[rb + t] = vb;
            }
        }
    }
}

// ---------------------------------------------------------------------------
// Launch
// ---------------------------------------------------------------------------
extern "C" void kernel_launch(void* const* d_in, const int* in_sizes, int n_in,
                              void* d_out, int out_size) {
    const float* x       = (const float*)d_in[0];
    const float* s       = (const float*)d_in[1];
    const int*   lengths = (const int*)  d_in[2];
    const float* fc1_w   = (const float*)d_in[3];
    const float* fc1_b   = (const float*)d_in[4];
    const float* alpha1  = (const float*)d_in[5];
    const float* conv1_w = (const float*)d_in[6];
    const float* conv1_b = (const float*)d_in[7];
    const float* fc2_w   = (const float*)d_in[8];
    const float* fc2_b   = (const float*)d_in[9];
    const float* alpha2  = (const float*)d_in[10];
    const float* conv2_w = (const float*)d_in[11];
    const float* conv2_b = (const float*)d_in[12];
    float* out = (float*)d_out;

    cudaFuncSetAttribute(conv_mma_kernel<false>,
                         cudaFuncAttributeMaxDynamicSharedMemorySize, CV_SMEM_TOTAL);
    cudaFuncSetAttribute(conv_mma_kernel<true>,
                         cudaFuncAttributeMaxDynamicSharedMemorySize, CV_SMEM_TOTAL);

    winsum_s_kernel<<<NB * NS, 256>>>(s);
    wprep_kernel<<<2048, 256>>>(conv1_w, conv2_w);

    dim3 agrid(NT / 64, NC / 64, NB);        // (32, 8, 16)
    dim3 cgrid(NT / 128, NC / 128, NB);      // (16, 4, 16)

    adawin_kernel<false><<<agrid, 256>>>(fc1_w, fc1_b, alpha1, x, lengths);
    conv_mma_kernel<false><<<cgrid, 256, CV_SMEM_TOTAL>>>(0, conv1_b, nullptr, nullptr);
    adawin_kernel<true><<<agrid, 256>>>(fc2_w, fc2_b, alpha2, x, lengths);
    conv_mma_kernel<true><<<cgrid, 256, CV_SMEM_TOTAL>>>(1, conv2_b, x, out);
}

// round 14
// speedup vs baseline: 1.2870x; 1.2870x over previous
#include <cuda_runtime.h>
#include <cuda_bf16.h>
#include <cstdint>
#include <math.h>

// Problem constants
#define NB 16
#define NC 512
#define NS 128
#define NT 2048
#define PADW 18    // W_LEN/2, W_LEN=37
#define TSTR 2050  // padded t rows for transposed conv input (1 zero row each end)

// ---------------------------------------------------------------------------
// Device scratch (no allocation allowed; zero-initialized at module load,
// pad rows of g_T* are never written so they stay zero -> implicit conv pad)
// ---------------------------------------------------------------------------
__device__ float g_ws[NB * NS * NT];                                   // win_sum(s)
__device__ float g_y2[(size_t)NB * NC * NT];                           // conv1 fp32 out
__device__ __align__(16) __nv_bfloat16 g_Thi[(size_t)NB * TSTR * NC];  // conv in, transposed, hi
__device__ __align__(16) __nv_bfloat16 g_Tlo[(size_t)NB * TSTR * NC];  // conv in, transposed, lo
__device__ __align__(16) __nv_bfloat16 g_wA[(size_t)2 * 6 * NC * NC];  // weights [conv][tap*2+spl][co][ci]

// ---------------------------------------------------------------------------
// mma.sync m16n8k16 bf16 (row.col), fp32 accumulate — sm_80+ baseline feature
// ---------------------------------------------------------------------------
__device__ __forceinline__ void mma16816(float* c, const uint32_t* a, const uint32_t* b) {
    asm volatile(
        "mma.sync.aligned.m16n8k16.row.col.f32.bf16.bf16.f32 "
        "{%0,%1,%2,%3}, {%4,%5,%6,%7}, {%8,%9}, {%0,%1,%2,%3};"
        : "+f"(c[0]), "+f"(c[1]), "+f"(c[2]), "+f"(c[3])
        : "r"(a[0]), "r"(a[1]), "r"(a[2]), "r"(a[3]), "r"(b[0]), "r"(b[1]));
}
__device__ __forceinline__ void ldsm4(uint32_t* r, uint32_t addr) {
    asm volatile("ldmatrix.sync.aligned.m8n8.x4.shared.b16 {%0,%1,%2,%3}, [%4];"
        : "=r"(r[0]), "=r"(r[1]), "=r"(r[2]), "=r"(r[3]) : "r"(addr));
}
__device__ __forceinline__ void cp_async16(uint32_t saddr, const void* gptr) {
    asm volatile("cp.async.cg.shared.global [%0], [%1], 16;" :: "r"(saddr), "l"(gptr));
}
#define CP_COMMIT() asm volatile("cp.async.commit_group;" ::: "memory")
#define CP_WAIT0()  asm volatile("cp.async.wait_group 0;" ::: "memory")

__device__ __forceinline__ uint32_t smem_u32(const void* p) {
    uint32_t a;
    asm("{ .reg .u64 t; cvta.to.shared.u64 t, %1; cvt.u32.u64 %0, t; }" : "=r"(a) : "l"(p));
    return a;
}

// ---------------------------------------------------------------------------
// Kernel 1: sliding window sum of s over t (window 37)
// ---------------------------------------------------------------------------
__global__ void __launch_bounds__(256) winsum_s_kernel(const float* __restrict__ s) {
    __shared__ float sm[NT + 2 * PADW];
    const int row = blockIdx.x;
    const float* src = s + (size_t)row * NT;
    const int tid = threadIdx.x;
    for (int t = tid; t < NT; t += 256) sm[PADW + t] = src[t];
    if (tid < PADW) { sm[tid] = 0.0f; sm[PADW + NT + tid] = 0.0f; }
    __syncthreads();

    const int t0 = tid * 8;
    float sum = 0.0f;
#pragma unroll
    for (int k = 0; k < 37; k++) sum += sm[t0 + k];
    float* dst = g_ws + (size_t)row * NT + t0;
    dst[0] = sum;
#pragma unroll
    for (int j = 1; j < 8; j++) {
        sum += sm[t0 + j + 36] - sm[t0 + j - 1];
        dst[j] = sum;
    }
}

// ---------------------------------------------------------------------------
// Kernel 1b: split + rearrange conv weights -> g_wA[conv][tap*2+spl][co][ci] bf16
// ---------------------------------------------------------------------------
__global__ void __launch_bounds__(256) wprep_kernel(const float* __restrict__ w1,
                                                    const float* __restrict__ w2) {
    const int idx = blockIdx.x * 256 + threadIdx.x;   // over 2*512*512
    const int conv = idx >> 18;
    const int rem = idx & 262143;
    const int co = rem >> 9, ci = rem & 511;
    const float* w = conv ? w2 : w1;
#pragma unroll
    for (int tap = 0; tap < 3; tap++) {
        const float v = w[(co * NC + ci) * 3 + tap];
        const __nv_bfloat16 h = __float2bfloat16(v);
        const __nv_bfloat16 l = __float2bfloat16(v - __bfloat162float(h));
        g_wA[((size_t)(conv * 6 + tap * 2 + 0) * NC + co) * NC + ci] = h;
        g_wA[((size_t)(conv * 6 + tap * 2 + 1) * NC + co) * NC + ci] = l;
    }
}

// ---------------------------------------------------------------------------
// Kernel 2: fused adawin stage (fp32 FFMA GEMM K=128 + epilogue).
// Epilogue emits leaky_relu result directly as TRANSPOSED bf16 hi/lo arrays
// g_T*[b][t+1][c] (conv input; taps become row offsets; pad rows stay zero).
// ---------------------------------------------------------------------------
template<bool STAGE2>
__global__ void __launch_bounds__(256) adawin_kernel(
    const float* __restrict__ fc_w, const float* __restrict__ fc_b,
    const float* __restrict__ alpha, const float* __restrict__ xin_p,
    const int* __restrict__ lengths)
{
    const int b  = blockIdx.z;
    const int c0 = blockIdx.y * 64;
    const int t0 = blockIdx.x * 64;
    const int tid = threadIdx.x;
    const int tx = tid & 15, ty = tid >> 4;

    __shared__ float Ag[16 * 68];
    __shared__ float Ab[16 * 68];
    __shared__ float Bs[16 * 68];

    float accg[4][4] = {};
    float accb[4][4] = {};

    const float* wsb = g_ws + (size_t)b * NS * NT;

    for (int k0 = 0; k0 < NS; k0 += 16) {
#pragma unroll
        for (int n = tid; n < 1024; n += 256) {
            const int kk = n & 15, i = n >> 4;
            Ag[kk * 68 + i] = fc_w[(c0 + i) * NS + k0 + kk];
            Ab[kk * 68 + i] = fc_w[(c0 + 512 + i) * NS + k0 + kk];
        }
#pragma unroll
        for (int n = tid; n < 1024; n += 256) {
            const int kk = n >> 6, j = n & 63;
            Bs[kk * 68 + j] = wsb[(k0 + kk) * NT + t0 + j];
        }
        __syncthreads();
#pragma unroll
        for (int kk = 0; kk < 16; kk++) {
            const float4 ag4 = *(const float4*)&Ag[kk * 68 + ty * 4];
            const float4 ab4 = *(const float4*)&Ab[kk * 68 + ty * 4];
            const float4 bv4 = *(const float4*)&Bs[kk * 68 + tx * 4];
            const float ag[4] = {ag4.x, ag4.y, ag4.z, ag4.w};
            const float ab[4] = {ab4.x, ab4.y, ab4.z, ab4.w};
            const float bv[4] = {bv4.x, bv4.y, bv4.z, bv4.w};
#pragma unroll
            for (int i = 0; i < 4; i++)
#pragma unroll
                for (int j = 0; j < 4; j++) {
                    accg[i][j] += ag[i] * bv[j];
                    accb[i][j] += ab[i] * bv[j];
                }
        }
        __syncthreads();
    }

    const int len = lengths[b];
    const float al = alpha[0];
    const float* xin = STAGE2 ? (const float*)g_y2 : xin_p;

    float vv[4][4];
#pragma unroll
    for (int i = 0; i < 4; i++) {
        const int c = c0 + ty * 4 + i;
        const float bg = fc_b[c];
        const float bb = fc_b[c + 512];
        const size_t rowoff = ((size_t)b * NC + c) * NT;
#pragma unroll
        for (int j = 0; j < 4; j++) {
            const int t = t0 + tx * 4 + j;
            const int lo = max(t - PADW, 0);
            const int hi = min(t + PADW, NT - 1);
            const float nwin = (float)(hi - lo + 1);
            int cnt = min(hi, len - 1) - lo + 1;
            cnt = max(cnt, 0);
            const float denom = (float)cnt + 1e-9f;
            const float m = (t < len) ? 1.0f : 0.0f;
            const float gam = (accg[i][j] + bg * nwin) / denom * m;
            const float bet = (accb[i][j] + bb * nwin) / denom * m;
            const float xn = tanhf(al * xin[rowoff + t]);
            float v = (1.0f + gam) * xn + bet;
            vv[i][j] = (v > 0.0f) ? v : 0.2f * v;   // leaky_relu 0.2
        }
    }

    // transposed bf16 hi/lo stores (4 c contiguous -> 8B packed stores)
#pragma unroll
    for (int j = 0; j < 4; j++) {
        const int t = t0 + tx * 4 + j;
        uint32_t hsh[2], hsl[2];
#pragma unroll
        for (int p = 0; p < 2; p++) {
            uint32_t h0, h1, l0, l1;
            {
                const float v = vv[p * 2 + 0][j];
                const __nv_bfloat16 h = __float2bfloat16(v);
                h0 = (uint32_t)__bfloat16_as_ushort(h);
                l0 = (uint32_t)__bfloat16_as_ushort(__float2bfloat16(v - __bfloat162float(h)));
            }
            {
                const float v = vv[p * 2 + 1][j];
                const __nv_bfloat16 h = __float2bfloat16(v);
                h1 = (uint32_t)__bfloat16_as_ushort(h);
                l1 = (uint32_t)__bfloat16_as_ushort(__float2bfloat16(v - __bfloat162float(h)));
            }
            hsh[p] = h0 | (h1 << 16);
            hsl[p] = l0 | (l1 << 16);
        }
        const size_t off = ((size_t)b * TSTR + t + 1) * NC + c0 + ty * 4;
        *(uint2*)&g_Thi[off] = make_uint2(hsh[0], hsh[1]);
        *(uint2*)&g_Tlo[off] = make_uint2(hsl[0], hsl[1]);
    }
}

// ---------------------------------------------------------------------------
// Kernel 3: conv1d k=3 via mma.sync bf16 (hi/lo 3-product split).
// CTA tile: M=128(co) x N=128(t); 8 warps (4m x 2n), warp tile 32x64.
// Pipelined: cp.async double-buffered SMEM, ldmatrix.x4 fragment loads.
// A SMEM: [tap*2+spl][128 co][32 ci] stride 80B.  B SMEM: [spl][130 t][32 ci].
// ---------------------------------------------------------------------------
#define CV_ASTRIDE 80                        // bytes per 32-ci row (40 bf16)
#define CV_ATILE   (128 * CV_ASTRIDE)        // 10240 B per (tap,spl) tile
#define CV_B_OFF   (6 * CV_ATILE)            // 61440
#define CV_BTILE   (130 * CV_ASTRIDE)        // 10400 B per spl
#define CV_BUF     (CV_B_OFF + 2 * CV_BTILE) // 82240 per buffer
#define CV_SMEM_TOTAL (2 * CV_BUF)           // 164480

__device__ __forceinline__ void cv_load(uint32_t sbuf, const __nv_bfloat16* __restrict__ wA,
                                        size_t tbase, int co0, int tg0, int k0, int tid) {
#pragma unroll
    for (int n = tid; n < 3072; n += 256) {
        const int ts = n >> 9, rem = n & 511;
        const int row = rem >> 2, c8 = rem & 3;
        cp_async16(sbuf + ts * CV_ATILE + row * CV_ASTRIDE + c8 * 16,
                   wA + ((size_t)ts * NC + co0 + row) * NC + k0 + c8 * 8);
    }
#pragma unroll
    for (int i = 0; i < 5; i++) {
        const int n = tid + i * 256;
        if (n < 1040) {
            const int spl = n / 520, rem = n % 520;
            const int row = rem >> 2, c8 = rem & 3;
            const __nv_bfloat16* src = (spl ? g_Tlo : g_Thi) + tbase;
            cp_async16(sbuf + CV_B_OFF + spl * CV_BTILE + row * CV_ASTRIDE + c8 * 16,
                       src + (size_t)(tg0 + row) * NC + k0 + c8 * 8);
        }
    }
}

template<bool FINAL>
__global__ void __launch_bounds__(256) conv_mma_kernel(
    int conv_sel, const float* __restrict__ bias,
    const float* __restrict__ xres, float* __restrict__ outp)
{
    extern __shared__ char smem[];
    const uint32_t sb = smem_u32(smem);
    const int tid = threadIdx.x;
    const int lane = tid & 31, wid = tid >> 5;
    const int wm = (wid & 3) * 32;        // warp m offset (co)
    const int wn = (wid >> 2) * 64;       // warp n offset (t)
    const int g = lane >> 2, q = lane & 3;

    const int b   = blockIdx.z;
    const int co0 = blockIdx.y * 128;
    const int tg0 = blockIdx.x * 128;

    const __nv_bfloat16* wA = g_wA + (size_t)conv_sel * 6 * NC * NC;
    const size_t tbase = (size_t)b * TSTR * NC;

    // ldmatrix per-lane address components
    const int rA   = wm + (lane & 7) + ((lane >> 3) & 1) * 8;   // A row (mi=0)
    const int kAof = (lane >> 4) * 16;                          // A k byte off
    const int rB0  = wn + ((lane >> 4) * 8) + (lane & 7);       // B row base (p=0,tap=0)
    const int kBof = ((lane >> 3) & 1) * 16;                    // B k byte off

    float acc[2][8][4] = {};

    // prologue: chunk 0
    cv_load(sb, wA, tbase, co0, tg0, 0, tid);
    CP_COMMIT();

    for (int chunk = 0; chunk < 16; chunk++) {
        CP_WAIT0();
        __syncthreads();
        if (chunk < 15) {
            cv_load(sb + ((chunk + 1) & 1) * CV_BUF, wA, tbase, co0, tg0, (chunk + 1) * 32, tid);
            CP_COMMIT();
        }
        const uint32_t sbuf = sb + (chunk & 1) * CV_BUF;
        const uint32_t sbB = sbuf + CV_B_OFF;

#pragma unroll
        for (int tap = 0; tap < 3; tap++) {
#pragma unroll
            for (int k16 = 0; k16 < 2; k16++) {
                uint32_t ah0[4], ah1[4], al0[4], al1[4];
                const uint32_t aBase = sbuf + (tap * 2) * CV_ATILE + rA * CV_ASTRIDE + k16 * 32 + kAof;
                ldsm4(ah0, aBase);
                ldsm4(ah1, aBase + 16 * CV_ASTRIDE);
                ldsm4(al0, aBase + CV_ATILE);
                ldsm4(al1, aBase + CV_ATILE + 16 * CV_ASTRIDE);
                const uint32_t kB = (uint32_t)(k16 * 32 + kBof);
#pragma unroll
                for (int p = 0; p < 4; p++) {
                    uint32_t bh[4], bl[4];
                    const uint32_t bAddr = sbB + (rB0 + tap + p * 16) * CV_ASTRIDE + kB;
                    ldsm4(bh, bAddr);
                    ldsm4(bl, bAddr + CV_BTILE);
                    mma16816(acc[0][2 * p],     ah0, bh);
                    mma16816(acc[0][2 * p],     ah0, bl);
                    mma16816(acc[0][2 * p],     al0, bh);
                    mma16816(acc[0][2 * p + 1], ah0, bh + 2);
                    mma16816(acc[0][2 * p + 1], ah0, bl + 2);
                    mma16816(acc[0][2 * p + 1], al0, bh + 2);
                    mma16816(acc[1][2 * p],     ah1, bh);
                    mma16816(acc[1][2 * p],     ah1, bl);
                    mma16816(acc[1][2 * p],     al1, bh);
                    mma16816(acc[1][2 * p + 1], ah1, bh + 2);
                    mma16816(acc[1][2 * p + 1], ah1, bl + 2);
                    mma16816(acc[1][2 * p + 1], al1, bh + 2);
                }
            }
        }
    }

    // ---- epilogue ----
    const float inv = 0.70710678118654752f;
#pragma unroll
    for (int mi = 0; mi < 2; mi++) {
        const int co_a = co0 + wm + mi * 16 + g;
        const int co_b = co_a + 8;
        const float bva = bias[co_a];
        const float bvb = bias[co_b];
        const size_t ra = ((size_t)b * NC + co_a) * NT;
        const size_t rb = ((size_t)b * NC + co_b) * NT;
#pragma unroll
        for (int nj = 0; nj < 8; nj++) {
            const int t = tg0 + wn + nj * 8 + q * 2;
            float2 va = make_float2(acc[mi][nj][0] + bva, acc[mi][nj][1] + bva);
            float2 vb = make_float2(acc[mi][nj][2] + bvb, acc[mi][nj][3] + bvb);
            if (FINAL) {
                const float2 xa = *(const float2*)&xres[ra + t];
                const float2 xb = *(const float2*)&xres[rb + t];
                va.x = (va.x + xa.x) * inv; va.y = (va.y + xa.y) * inv;
                vb.x = (vb.x + xb.x) * inv; vb.y = (vb.y + xb.y) * inv;
                *(float2*)&outp[ra + t] = va;
                *(float2*)&outp[rb + t] = vb;
            } else {
                *(float2*)&g_y2[ra + t] = va;
                *(float2*)&g_y2[rb + t] = vb;
            }
        }
    }
}

// ---------------------------------------------------------------------------
// Launch
// ---------------------------------------------------------------------------
extern "C" void kernel_launch(void* const* d_in, const int* in_sizes, int n_in,
                              void* d_out, int out_size) {
    const float* x       = (const float*)d_in[0];
    const float* s       = (const float*)d_in[1];
    const int*   lengths = (const int*)  d_in[2];
    const float* fc1_w   = (const float*)d_in[3];
    const float* fc1_b   = (const float*)d_in[4];
    const float* alpha1  = (const float*)d_in[5];
    const float* conv1_w = (const float*)d_in[6];
    const float* conv1_b = (const float*)d_in[7];
    const float* fc2_w   = (const float*)d_in[8];
    const float* fc2_b   = (const float*)d_in[9];
    const float* alpha2  = (const float*)d_in[10];
    const float* conv2_w = (const float*)d_in[11];
    const float* conv2_b = (const float*)d_in[12];
    float* out = (float*)d_out;

    cudaFuncSetAttribute(conv_mma_kernel<false>,
                         cudaFuncAttributeMaxDynamicSharedMemorySize, CV_SMEM_TOTAL);
    cudaFuncSetAttribute(conv_mma_kernel<true>,
                         cudaFuncAttributeMaxDynamicSharedMemorySize, CV_SMEM_TOTAL);

    winsum_s_kernel<<<NB * NS, 256>>>(s);
    wprep_kernel<<<2048, 256>>>(conv1_w, conv2_w);

    dim3 agrid(NT / 64, NC / 64, NB);        // (32, 8, 16)
    dim3 cgrid(NT / 128, NC / 128, NB);      // (16, 4, 16)

    adawin_kernel<false><<<agrid, 256>>>(fc1_w, fc1_b, alpha1, x, lengths);
    conv_mma_kernel<false><<<cgrid, 256, CV_SMEM_TOTAL>>>(0, conv1_b, nullptr, nullptr);
    adawin_kernel<true><<<agrid, 256>>>(fc2_w, fc2_b, alpha2, x, lengths);
    conv_mma_kernel<true><<<cgrid, 256, CV_SMEM_TOTAL>>>(1, conv2_b, x, out);
}

// round 15
// speedup vs baseline: 1.2881x; 1.0009x over previous
#include <cuda_runtime.h>
#include <cuda_bf16.h>
#include <cstdint>
#include <math.h>

// Problem constants
#define NB 16
#define NC 512
#define NS 128
#define NT 2048
#define PADW 18    // W_LEN/2, W_LEN=37
#define TSTR 2050  // padded t rows for transposed conv input (1 zero row each end)

// ---------------------------------------------------------------------------
// Device scratch (no allocation allowed; zero-initialized at module load,
// pad rows of g_T* are never written so they stay zero -> implicit conv pad)
// ---------------------------------------------------------------------------
__device__ float g_ws[NB * NS * NT];                                   // win_sum(s)
__device__ float g_y2[(size_t)NB * NC * NT];                           // conv1 fp32 out
__device__ __align__(16) __nv_bfloat16 g_Thi[(size_t)NB * TSTR * NC];  // conv in, transposed, hi
__device__ __align__(16) __nv_bfloat16 g_Tlo[(size_t)NB * TSTR * NC];  // conv in, transposed, lo
__device__ __align__(16) __nv_bfloat16 g_wA[(size_t)2 * 6 * NC * NC];  // weights [conv][tap*2+spl][co][ci]

// ---------------------------------------------------------------------------
// mma.sync m16n8k16 bf16 (row.col), fp32 accumulate — sm_80+ baseline feature
// ---------------------------------------------------------------------------
__device__ __forceinline__ void mma16816(float* c, const uint32_t* a, const uint32_t* b) {
    asm volatile(
        "mma.sync.aligned.m16n8k16.row.col.f32.bf16.bf16.f32 "
        "{%0,%1,%2,%3}, {%4,%5,%6,%7}, {%8,%9}, {%0,%1,%2,%3};"
        : "+f"(c[0]), "+f"(c[1]), "+f"(c[2]), "+f"(c[3])
        : "r"(a[0]), "r"(a[1]), "r"(a[2]), "r"(a[3]), "r"(b[0]), "r"(b[1]));
}
__device__ __forceinline__ void ldsm4(uint32_t* r, uint32_t addr) {
    asm volatile("ldmatrix.sync.aligned.m8n8.x4.shared.b16 {%0,%1,%2,%3}, [%4];"
        : "=r"(r[0]), "=r"(r[1]), "=r"(r[2]), "=r"(r[3]) : "r"(addr));
}
__device__ __forceinline__ void cp_async16(uint32_t saddr, const void* gptr) {
    asm volatile("cp.async.cg.shared.global [%0], [%1], 16;" :: "r"(saddr), "l"(gptr));
}
#define CP_COMMIT() asm volatile("cp.async.commit_group;" ::: "memory")
#define CP_WAIT0()  asm volatile("cp.async.wait_group 0;" ::: "memory")

__device__ __forceinline__ uint32_t smem_u32(const void* p) {
    uint32_t a;
    asm("{ .reg .u64 t; cvta.to.shared.u64 t, %1; cvt.u32.u64 %0, t; }" : "=r"(a) : "l"(p));
    return a;
}

// ---------------------------------------------------------------------------
// Kernel 1: sliding window sum of s over t (window 37)
// ---------------------------------------------------------------------------
__global__ void __launch_bounds__(256) winsum_s_kernel(const float* __restrict__ s) {
    __shared__ float sm[NT + 2 * PADW];
    const int row = blockIdx.x;
    const float* src = s + (size_t)row * NT;
    const int tid = threadIdx.x;
    for (int t = tid; t < NT; t += 256) sm[PADW + t] = src[t];
    if (tid < PADW) { sm[tid] = 0.0f; sm[PADW + NT + tid] = 0.0f; }
    __syncthreads();

    const int t0 = tid * 8;
    float sum = 0.0f;
#pragma unroll
    for (int k = 0; k < 37; k++) sum += sm[t0 + k];
    float* dst = g_ws + (size_t)row * NT + t0;
    dst[0] = sum;
#pragma unroll
    for (int j = 1; j < 8; j++) {
        sum += sm[t0 + j + 36] - sm[t0 + j - 1];
        dst[j] = sum;
    }
}

// ---------------------------------------------------------------------------
// Kernel 1b: split + rearrange conv weights -> g_wA[conv][tap*2+spl][co][ci] bf16
// ---------------------------------------------------------------------------
__global__ void __launch_bounds__(256) wprep_kernel(const float* __restrict__ w1,
                                                    const float* __restrict__ w2) {
    const int idx = blockIdx.x * 256 + threadIdx.x;   // over 2*512*512
    const int conv = idx >> 18;
    const int rem = idx & 262143;
    const int co = rem >> 9, ci = rem & 511;
    const float* w = conv ? w2 : w1;
#pragma unroll
    for (int tap = 0; tap < 3; tap++) {
        const float v = w[(co * NC + ci) * 3 + tap];
        const __nv_bfloat16 h = __float2bfloat16(v);
        const __nv_bfloat16 l = __float2bfloat16(v - __bfloat162float(h));
        g_wA[((size_t)(conv * 6 + tap * 2 + 0) * NC + co) * NC + ci] = h;
        g_wA[((size_t)(conv * 6 + tap * 2 + 1) * NC + co) * NC + ci] = l;
    }
}

// ---------------------------------------------------------------------------
// Kernel 2: fused adawin stage (fp32 FFMA GEMM K=128 + epilogue).
// Epilogue emits leaky_relu result directly as TRANSPOSED bf16 hi/lo arrays
// g_T*[b][t+1][c] (conv input; taps become row offsets; pad rows stay zero).
// ---------------------------------------------------------------------------
template<bool STAGE2>
__global__ void __launch_bounds__(256) adawin_kernel(
    const float* __restrict__ fc_w, const float* __restrict__ fc_b,
    const float* __restrict__ alpha, const float* __restrict__ xin_p,
    const int* __restrict__ lengths)
{
    const int b  = blockIdx.z;
    const int c0 = blockIdx.y * 64;
    const int t0 = blockIdx.x * 64;
    const int tid = threadIdx.x;
    const int tx = tid & 15, ty = tid >> 4;

    __shared__ float Ag[16 * 68];
    __shared__ float Ab[16 * 68];
    __shared__ float Bs[16 * 68];

    float accg[4][4] = {};
    float accb[4][4] = {};

    const float* wsb = g_ws + (size_t)b * NS * NT;

    for (int k0 = 0; k0 < NS; k0 += 16) {
#pragma unroll
        for (int n = tid; n < 1024; n += 256) {
            const int kk = n & 15, i = n >> 4;
            Ag[kk * 68 + i] = fc_w[(c0 + i) * NS + k0 + kk];
            Ab[kk * 68 + i] = fc_w[(c0 + 512 + i) * NS + k0 + kk];
        }
#pragma unroll
        for (int n = tid; n < 1024; n += 256) {
            const int kk = n >> 6, j = n & 63;
            Bs[kk * 68 + j] = wsb[(k0 + kk) * NT + t0 + j];
        }
        __syncthreads();
#pragma unroll
        for (int kk = 0; kk < 16; kk++) {
            const float4 ag4 = *(const float4*)&Ag[kk * 68 + ty * 4];
            const float4 ab4 = *(const float4*)&Ab[kk * 68 + ty * 4];
            const float4 bv4 = *(const float4*)&Bs[kk * 68 + tx * 4];
            const float ag[4] = {ag4.x, ag4.y, ag4.z, ag4.w};
            const float ab[4] = {ab4.x, ab4.y, ab4.z, ab4.w};
            const float bv[4] = {bv4.x, bv4.y, bv4.z, bv4.w};
#pragma unroll
            for (int i = 0; i < 4; i++)
#pragma unroll
                for (int j = 0; j < 4; j++) {
                    accg[i][j] += ag[i] * bv[j];
                    accb[i][j] += ab[i] * bv[j];
                }
        }
        __syncthreads();
    }

    const int len = lengths[b];
    const float al = alpha[0];
    const float* xin = STAGE2 ? (const float*)g_y2 : xin_p;

    float vv[4][4];
#pragma unroll
    for (int i = 0; i < 4; i++) {
        const int c = c0 + ty * 4 + i;
        const float bg = fc_b[c];
        const float bb = fc_b[c + 512];
        const size_t rowoff = ((size_t)b * NC + c) * NT;
#pragma unroll
        for (int j = 0; j < 4; j++) {
            const int t = t0 + tx * 4 + j;
            const int lo = max(t - PADW, 0);
            const int hi = min(t + PADW, NT - 1);
            const float nwin = (float)(hi - lo + 1);
            int cnt = min(hi, len - 1) - lo + 1;
            cnt = max(cnt, 0);
            const float denom = (float)cnt + 1e-9f;
            const float m = (t < len) ? 1.0f : 0.0f;
            const float gam = (accg[i][j] + bg * nwin) / denom * m;
            const float bet = (accb[i][j] + bb * nwin) / denom * m;
            const float xn = tanhf(al * xin[rowoff + t]);
            float v = (1.0f + gam) * xn + bet;
            vv[i][j] = (v > 0.0f) ? v : 0.2f * v;   // leaky_relu 0.2
        }
    }

    // transposed bf16 hi/lo stores (4 c contiguous -> 8B packed stores)
#pragma unroll
    for (int j = 0; j < 4; j++) {
        const int t = t0 + tx * 4 + j;
        uint32_t hsh[2], hsl[2];
#pragma unroll
        for (int p = 0; p < 2; p++) {
            uint32_t h0, h1, l0, l1;
            {
                const float v = vv[p * 2 + 0][j];
                const __nv_bfloat16 h = __float2bfloat16(v);
                h0 = (uint32_t)__bfloat16_as_ushort(h);
                l0 = (uint32_t)__bfloat16_as_ushort(__float2bfloat16(v - __bfloat162float(h)));
            }
            {
                const float v = vv[p * 2 + 1][j];
                const __nv_bfloat16 h = __float2bfloat16(v);
                h1 = (uint32_t)__bfloat16_as_ushort(h);
                l1 = (uint32_t)__bfloat16_as_ushort(__float2bfloat16(v - __bfloat162float(h)));
            }
            hsh[p] = h0 | (h1 << 16);
            hsl[p] = l0 | (l1 << 16);
        }
        const size_t off = ((size_t)b * TSTR + t + 1) * NC + c0 + ty * 4;
        *(uint2*)&g_Thi[off] = make_uint2(hsh[0], hsh[1]);
        *(uint2*)&g_Tlo[off] = make_uint2(hsl[0], hsl[1]);
    }
}

// ---------------------------------------------------------------------------
// Kernel 3: conv1d k=3 via mma.sync bf16 (hi/lo 3-product split).
// CTA tile: M=128(co) x N=128(t); 8 warps (4m x 2n), warp tile 32x64.
// Pipelined: cp.async double-buffered SMEM, ldmatrix.x4 fragment loads.
// A SMEM: [tap*2+spl][128 co][32 ci] stride 80B.  B SMEM: [spl][130 t][32 ci].
// ---------------------------------------------------------------------------
#define CV_ASTRIDE 80                        // bytes per 32-ci row (40 bf16)
#define CV_ATILE   (128 * CV_ASTRIDE)        // 10240 B per (tap,spl) tile
#define CV_B_OFF   (6 * CV_ATILE)            // 61440
#define CV_BTILE   (130 * CV_ASTRIDE)        // 10400 B per spl
#define CV_BUF     (CV_B_OFF + 2 * CV_BTILE) // 82240 per buffer
#define CV_SMEM_TOTAL (2 * CV_BUF)           // 164480

__device__ __forceinline__ void cv_load(uint32_t sbuf, const __nv_bfloat16* __restrict__ wA,
                                        size_t tbase, int co0, int tg0, int k0, int tid) {
#pragma unroll
    for (int n = tid; n < 3072; n += 256) {
        const int ts = n >> 9, rem = n & 511;
        const int row = rem >> 2, c8 = rem & 3;
        cp_async16(sbuf + ts * CV_ATILE + row * CV_ASTRIDE + c8 * 16,
                   wA + ((size_t)ts * NC + co0 + row) * NC + k0 + c8 * 8);
    }
#pragma unroll
    for (int i = 0; i < 5; i++) {
        const int n = tid + i * 256;
        if (n < 1040) {
            const int spl = n / 520, rem = n % 520;
            const int row = rem >> 2, c8 = rem & 3;
            const __nv_bfloat16* src = (spl ? g_Tlo : g_Thi) + tbase;
            cp_async16(sbuf + CV_B_OFF + spl * CV_BTILE + row * CV_ASTRIDE + c8 * 16,
                       src + (size_t)(tg0 + row) * NC + k0 + c8 * 8);
        }
    }
}

template<bool FINAL>
__global__ void __launch_bounds__(256) conv_mma_kernel(
    int conv_sel, const float* __restrict__ bias,
    const float* __restrict__ xres, float* __restrict__ outp)
{
    extern __shared__ char smem[];
    const uint32_t sb = smem_u32(smem);
    const int tid = threadIdx.x;
    const int lane = tid & 31, wid = tid >> 5;
    const int wm = (wid & 3) * 32;        // warp m offset (co)
    const int wn = (wid >> 2) * 64;       // warp n offset (t)
    const int g = lane >> 2, q = lane & 3;

    const int b   = blockIdx.z;
    const int co0 = blockIdx.y * 128;
    const int tg0 = blockIdx.x * 128;

    const __nv_bfloat16* wA = g_wA + (size_t)conv_sel * 6 * NC * NC;
    const size_t tbase = (size_t)b * TSTR * NC;

    // ldmatrix per-lane address components
    const int rA   = wm + (lane & 7) + ((lane >> 3) & 1) * 8;   // A row (mi=0)
    const int kAof = (lane >> 4) * 16;                          // A k byte off
    const int rB0  = wn + ((lane >> 4) * 8) + (lane & 7);       // B row base (p=0,tap=0)
    const int kBof = ((lane >> 3) & 1) * 16;                    // B k byte off

    float acc[2][8][4] = {};

    // prologue: chunk 0
    cv_load(sb, wA, tbase, co0, tg0, 0, tid);
    CP_COMMIT();

    for (int chunk = 0; chunk < 16; chunk++) {
        CP_WAIT0();
        __syncthreads();
        if (chunk < 15) {
            cv_load(sb + ((chunk + 1) & 1) * CV_BUF, wA, tbase, co0, tg0, (chunk + 1) * 32, tid);
            CP_COMMIT();
        }
        const uint32_t sbuf = sb + (chunk & 1) * CV_BUF;
        const uint32_t sbB = sbuf + CV_B_OFF;

#pragma unroll
        for (int tap = 0; tap < 3; tap++) {
#pragma unroll
            for (int k16 = 0; k16 < 2; k16++) {
                uint32_t ah0[4], ah1[4], al0[4], al1[4];
                const uint32_t aBase = sbuf + (tap * 2) * CV_ATILE + rA * CV_ASTRIDE + k16 * 32 + kAof;
                ldsm4(ah0, aBase);
                ldsm4(ah1, aBase + 16 * CV_ASTRIDE);
                ldsm4(al0, aBase + CV_ATILE);
                ldsm4(al1, aBase + CV_ATILE + 16 * CV_ASTRIDE);
                const uint32_t kB = (uint32_t)(k16 * 32 + kBof);
#pragma unroll
                for (int p = 0; p < 4; p++) {
                    uint32_t bh[4], bl[4];
                    const uint32_t bAddr = sbB + (rB0 + tap + p * 16) * CV_ASTRIDE + kB;
                    ldsm4(bh, bAddr);
                    ldsm4(bl, bAddr + CV_BTILE);
                    mma16816(acc[0][2 * p],     ah0, bh);
                    mma16816(acc[0][2 * p],     ah0, bl);
                    mma16816(acc[0][2 * p],     al0, bh);
                    mma16816(acc[0][2 * p + 1], ah0, bh + 2);
                    mma16816(acc[0][2 * p + 1], ah0, bl + 2);
                    mma16816(acc[0][2 * p + 1], al0, bh + 2);
                    mma16816(acc[1][2 * p],     ah1, bh);
                    mma16816(acc[1][2 * p],     ah1, bl);
                    mma16816(acc[1][2 * p],     al1, bh);
                    mma16816(acc[1][2 * p + 1], ah1, bh + 2);
                    mma16816(acc[1][2 * p + 1], ah1, bl + 2);
                    mma16816(acc[1][2 * p + 1], al1, bh + 2);
                }
            }
        }
    }

    // ---- epilogue ----
    const float inv = 0.70710678118654752f;
#pragma unroll
    for (int mi = 0; mi < 2; mi++) {
        const int co_a = co0 + wm + mi * 16 + g;
        const int co_b = co_a + 8;
        const float bva = bias[co_a];
        const float bvb = bias[co_b];
        const size_t ra = ((size_t)b * NC + co_a) * NT;
        const size_t rb = ((size_t)b * NC + co_b) * NT;
#pragma unroll
        for (int nj = 0; nj < 8; nj++) {
            const int t = tg0 + wn + nj * 8 + q * 2;
            float2 va = make_float2(acc[mi][nj][0] + bva, acc[mi][nj][1] + bva);
            float2 vb = make_float2(acc[mi][nj][2] + bvb, acc[mi][nj][3] + bvb);
            if (FINAL) {
                const float2 xa = *(const float2*)&xres[ra + t];
                const float2 xb = *(const float2*)&xres[rb + t];
                va.x = (va.x + xa.x) * inv; va.y = (va.y + xa.y) * inv;
                vb.x = (vb.x + xb.x) * inv; vb.y = (vb.y + xb.y) * inv;
                *(float2*)&outp[ra + t] = va;
                *(float2*)&outp[rb + t] = vb;
            } else {
                *(float2*)&g_y2[ra + t] = va;
                *(float2*)&g_y2[rb + t] = vb;
            }
        }
    }
}

// ---------------------------------------------------------------------------
// Launch
// ---------------------------------------------------------------------------
extern "C" void kernel_launch(void* const* d_in, const int* in_sizes, int n_in,
                              void* d_out, int out_size) {
    const float* x       = (const float*)d_in[0];
    const float* s       = (const float*)d_in[1];
    const int*   lengths = (const int*)  d_in[2];
    const float* fc1_w   = (const float*)d_in[3];
    const float* fc1_b   = (const float*)d_in[4];
    const float* alpha1  = (const float*)d_in[5];
    const float* conv1_w = (const float*)d_in[6];
    const float* conv1_b = (const float*)d_in[7];
    const float* fc2_w   = (const float*)d_in[8];
    const float* fc2_b   = (const float*)d_in[9];
    const float* alpha2  = (const float*)d_in[10];
    const float* conv2_w = (const float*)d_in[11];
    const float* conv2_b = (const float*)d_in[12];
    float* out = (float*)d_out;

    cudaFuncSetAttribute(conv_mma_kernel<false>,
                         cudaFuncAttributeMaxDynamicSharedMemorySize, CV_SMEM_TOTAL);
    cudaFuncSetAttribute(conv_mma_kernel<true>,
                         cudaFuncAttributeMaxDynamicSharedMemorySize, CV_SMEM_TOTAL);

    winsum_s_kernel<<<NB * NS, 256>>>(s);
    wprep_kernel<<<2048, 256>>>(conv1_w, conv2_w);

    dim3 agrid(NT / 64, NC / 64, NB);        // (32, 8, 16)
    dim3 cgrid(NT / 128, NC / 128, NB);      // (16, 4, 16)

    adawin_kernel<false><<<agrid, 256>>>(fc1_w, fc1_b, alpha1, x, lengths);
    conv_mma_kernel<false><<<cgrid, 256, CV_SMEM_TOTAL>>>(0, conv1_b, nullptr, nullptr);
    adawin_kernel<true><<<agrid, 256>>>(fc2_w, fc2_b, alpha2, x, lengths);
    conv_mma_kernel<true><<<cgrid, 256, CV_SMEM_TOTAL>>>(1, conv2_b, x, out);
}

// round 16
// speedup vs baseline: 1.5570x; 1.2087x over previous
#include <cuda_runtime.h>
#include <cuda_bf16.h>
#include <cuda_fp16.h>
#include <cstdint>
#include <math.h>

// Problem constants
#define NB 16
#define NC 512
#define NS 128
#define NT 2048
#define PADW 18    // W_LEN/2, W_LEN=37
#define TSTR 2050  // padded t rows for transposed conv input (1 zero row each end)

// ---------------------------------------------------------------------------
// Device scratch (no allocation allowed; zero-initialized at module load,
// pad rows of g_T* are never written so they stay zero -> implicit conv pad)
// ---------------------------------------------------------------------------
__device__ float g_ws[NB * NS * NT];                              // win_sum(s)
__device__ float g_y2[(size_t)NB * NC * NT];                      // conv1 fp32 out
__device__ __align__(16) __half g_Thi[(size_t)NB * TSTR * NC];    // conv in, transposed, hi (fp16)
__device__ __align__(16) __half g_Tlo[(size_t)NB * TSTR * NC];    // conv in, transposed, lo (fp16)
__device__ __align__(16) __half g_wA[(size_t)2 * 3 * NC * NC];    // weights [conv][tap][co][ci] fp16

// ---------------------------------------------------------------------------
// mma.sync m16n8k16 fp16 (row.col), fp32 accumulate — sm_80+ baseline feature
// ---------------------------------------------------------------------------
__device__ __forceinline__ void mma16816(float* c, const uint32_t* a, const uint32_t* b) {
    asm volatile(
        "mma.sync.aligned.m16n8k16.row.col.f32.f16.f16.f32 "
        "{%0,%1,%2,%3}, {%4,%5,%6,%7}, {%8,%9}, {%0,%1,%2,%3};"
        : "+f"(c[0]), "+f"(c[1]), "+f"(c[2]), "+f"(c[3])
        : "r"(a[0]), "r"(a[1]), "r"(a[2]), "r"(a[3]), "r"(b[0]), "r"(b[1]));
}
__device__ __forceinline__ void ldsm4(uint32_t* r, uint32_t addr) {
    asm volatile("ldmatrix.sync.aligned.m8n8.x4.shared.b16 {%0,%1,%2,%3}, [%4];"
        : "=r"(r[0]), "=r"(r[1]), "=r"(r[2]), "=r"(r[3]) : "r"(addr));
}
__device__ __forceinline__ void cp_async16(uint32_t saddr, const void* gptr) {
    asm volatile("cp.async.cg.shared.global [%0], [%1], 16;" :: "r"(saddr), "l"(gptr));
}
#define CP_COMMIT() asm volatile("cp.async.commit_group;" ::: "memory")
#define CP_WAIT0()  asm volatile("cp.async.wait_group 0;" ::: "memory")
#define CP_WAIT1()  asm volatile("cp.async.wait_group 1;" ::: "memory")

__device__ __forceinline__ uint32_t smem_u32(const void* p) {
    uint32_t a;
    asm("{ .reg .u64 t; cvta.to.shared.u64 t, %1; cvt.u32.u64 %0, t; }" : "=r"(a) : "l"(p));
    return a;
}

// ---------------------------------------------------------------------------
// Kernel 1: sliding window sum of s over t (window 37)
// ---------------------------------------------------------------------------
__global__ void __launch_bounds__(256) winsum_s_kernel(const float* __restrict__ s) {
    __shared__ float sm[NT + 2 * PADW];
    const int row = blockIdx.x;
    const float* src = s + (size_t)row * NT;
    const int tid = threadIdx.x;
    for (int t = tid; t < NT; t += 256) sm[PADW + t] = src[t];
    if (tid < PADW) { sm[tid] = 0.0f; sm[PADW + NT + tid] = 0.0f; }
    __syncthreads();

    const int t0 = tid * 8;
    float sum = 0.0f;
#pragma unroll
    for (int k = 0; k < 37; k++) sum += sm[t0 + k];
    float* dst = g_ws + (size_t)row * NT + t0;
    dst[0] = sum;
#pragma unroll
    for (int j = 1; j < 8; j++) {
        sum += sm[t0 + j + 36] - sm[t0 + j - 1];
        dst[j] = sum;
    }
}

// ---------------------------------------------------------------------------
// Kernel 1b: rearrange conv weights -> g_wA[conv][tap][co][ci] fp16
// ---------------------------------------------------------------------------
__global__ void __launch_bounds__(256) wprep_kernel(const float* __restrict__ w1,
                                                    const float* __restrict__ w2) {
    const int idx = blockIdx.x * 256 + threadIdx.x;   // over 2*512*512
    const int conv = idx >> 18;
    const int rem = idx & 262143;
    const int co = rem >> 9, ci = rem & 511;
    const float* w = conv ? w2 : w1;
#pragma unroll
    for (int tap = 0; tap < 3; tap++) {
        const float v = w[(co * NC + ci) * 3 + tap];
        g_wA[((size_t)(conv * 3 + tap) * NC + co) * NC + ci] = __float2half(v);
    }
}

// ---------------------------------------------------------------------------
// Kernel 2: fused adawin stage (fp32 FFMA GEMM K=128 + epilogue).
// Epilogue emits leaky_relu result directly as TRANSPOSED fp16 hi/lo arrays
// g_T*[b][t+1][c] (conv input; taps become row offsets; pad rows stay zero).
// ---------------------------------------------------------------------------
template<bool STAGE2>
__global__ void __launch_bounds__(256) adawin_kernel(
    const float* __restrict__ fc_w, const float* __restrict__ fc_b,
    const float* __restrict__ alpha, const float* __restrict__ xin_p,
    const int* __restrict__ lengths)
{
    const int b  = blockIdx.z;
    const int c0 = blockIdx.y * 64;
    const int t0 = blockIdx.x * 64;
    const int tid = threadIdx.x;
    const int tx = tid & 15, ty = tid >> 4;

    __shared__ float Ag[16 * 68];
    __shared__ float Ab[16 * 68];
    __shared__ float Bs[16 * 68];

    float accg[4][4] = {};
    float accb[4][4] = {};

    const float* wsb = g_ws + (size_t)b * NS * NT;

    for (int k0 = 0; k0 < NS; k0 += 16) {
#pragma unroll
        for (int n = tid; n < 1024; n += 256) {
            const int kk = n & 15, i = n >> 4;
            Ag[kk * 68 + i] = fc_w[(c0 + i) * NS + k0 + kk];
            Ab[kk * 68 + i] = fc_w[(c0 + 512 + i) * NS + k0 + kk];
        }
#pragma unroll
        for (int n = tid; n < 1024; n += 256) {
            const int kk = n >> 6, j = n & 63;
            Bs[kk * 68 + j] = wsb[(k0 + kk) * NT + t0 + j];
        }
        __syncthreads();
#pragma unroll
        for (int kk = 0; kk < 16; kk++) {
            const float4 ag4 = *(const float4*)&Ag[kk * 68 + ty * 4];
            const float4 ab4 = *(const float4*)&Ab[kk * 68 + ty * 4];
            const float4 bv4 = *(const float4*)&Bs[kk * 68 + tx * 4];
            const float ag[4] = {ag4.x, ag4.y, ag4.z, ag4.w};
            const float ab[4] = {ab4.x, ab4.y, ab4.z, ab4.w};
            const float bv[4] = {bv4.x, bv4.y, bv4.z, bv4.w};
#pragma unroll
            for (int i = 0; i < 4; i++)
#pragma unroll
                for (int j = 0; j < 4; j++) {
                    accg[i][j] += ag[i] * bv[j];
                    accb[i][j] += ab[i] * bv[j];
                }
        }
        __syncthreads();
    }

    const int len = lengths[b];
    const float al = alpha[0];
    const float* xin = STAGE2 ? (const float*)g_y2 : xin_p;

    float vv[4][4];
#pragma unroll
    for (int i = 0; i < 4; i++) {
        const int c = c0 + ty * 4 + i;
        const float bg = fc_b[c];
        const float bb = fc_b[c + 512];
        const size_t rowoff = ((size_t)b * NC + c) * NT;
#pragma unroll
        for (int j = 0; j < 4; j++) {
            const int t = t0 + tx * 4 + j;
            const int lo = max(t - PADW, 0);
            const int hi = min(t + PADW, NT - 1);
            const float nwin = (float)(hi - lo + 1);
            int cnt = min(hi, len - 1) - lo + 1;
            cnt = max(cnt, 0);
            const float denom = (float)cnt + 1e-9f;
            const float m = (t < len) ? 1.0f : 0.0f;
            const float gam = (accg[i][j] + bg * nwin) / denom * m;
            const float bet = (accb[i][j] + bb * nwin) / denom * m;
            const float xn = tanhf(al * xin[rowoff + t]);
            float v = (1.0f + gam) * xn + bet;
            vv[i][j] = (v > 0.0f) ? v : 0.2f * v;   // leaky_relu 0.2
        }
    }

    // transposed fp16 hi/lo stores (4 c contiguous -> 8B packed stores)
#pragma unroll
    for (int j = 0; j < 4; j++) {
        const int t = t0 + tx * 4 + j;
        uint32_t hsh[2], hsl[2];
#pragma unroll
        for (int p = 0; p < 2; p++) {
            uint32_t h0, h1, l0, l1;
            {
                const float v = vv[p * 2 + 0][j];
                const __half h = __float2half(v);
                h0 = (uint32_t)__half_as_ushort(h);
                l0 = (uint32_t)__half_as_ushort(__float2half(v - __half2float(h)));
            }
            {
                const float v = vv[p * 2 + 1][j];
                const __half h = __float2half(v);
                h1 = (uint32_t)__half_as_ushort(h);
                l1 = (uint32_t)__half_as_ushort(__float2half(v - __half2float(h)));
            }
            hsh[p] = h0 | (h1 << 16);
            hsl[p] = l0 | (l1 << 16);
        }
        const size_t off = ((size_t)b * TSTR + t + 1) * NC + c0 + ty * 4;
        *(uint2*)&g_Thi[off] = make_uint2(hsh[0], hsh[1]);
        *(uint2*)&g_Tlo[off] = make_uint2(hsl[0], hsl[1]);
    }
}

// ---------------------------------------------------------------------------
// Kernel 3: conv1d k=3 via mma.sync fp16 (weights single, data hi/lo: 2 products).
// CTA tile: M=128(co) x N=128(t); 8 warps (4m x 2n), warp tile 32x64.
// Triple-buffered cp.async (depth-2 prefetch), ldmatrix.x4 fragment loads.
// A SMEM: [tap][128 co][32 ci] stride 80B.  B SMEM: [spl][130 t][32 ci].
// ---------------------------------------------------------------------------
#define CV_ASTRIDE 80                        // bytes per 32-ci row (40 fp16)
#define CV_ATILE   (128 * CV_ASTRIDE)        // 10240 B per tap tile
#define CV_B_OFF   (3 * CV_ATILE)            // 30720
#define CV_BTILE   (130 * CV_ASTRIDE)        // 10400 B per spl
#define CV_BUF     (CV_B_OFF + 2 * CV_BTILE) // 51520 per buffer
#define CV_SMEM_TOTAL (3 * CV_BUF)           // 154560

__device__ __forceinline__ void cv_load(uint32_t sbuf, const __half* __restrict__ wA,
                                        size_t tbase, int co0, int tg0, int k0, int tid) {
#pragma unroll
    for (int n = tid; n < 1536; n += 256) {
        const int ts = n >> 9, rem = n & 511;
        const int row = rem >> 2, c8 = rem & 3;
        cp_async16(sbuf + ts * CV_ATILE + row * CV_ASTRIDE + c8 * 16,
                   wA + ((size_t)ts * NC + co0 + row) * NC + k0 + c8 * 8);
    }
#pragma unroll
    for (int i = 0; i < 5; i++) {
        const int n = tid + i * 256;
        if (n < 1040) {
            const int spl = n / 520, rem = n % 520;
            const int row = rem >> 2, c8 = rem & 3;
            const __half* src = (spl ? g_Tlo : g_Thi) + tbase;
            cp_async16(sbuf + CV_B_OFF + spl * CV_BTILE + row * CV_ASTRIDE + c8 * 16,
                       src + (size_t)(tg0 + row) * NC + k0 + c8 * 8);
        }
    }
}

template<bool FINAL>
__global__ void __launch_bounds__(256) conv_mma_kernel(
    int conv_sel, const float* __restrict__ bias,
    const float* __restrict__ xres, float* __restrict__ outp)
{
    extern __shared__ char smem[];
    const uint32_t sb = smem_u32(smem);
    const int tid = threadIdx.x;
    const int lane = tid & 31, wid = tid >> 5;
    const int wm = (wid & 3) * 32;        // warp m offset (co)
    const int wn = (wid >> 2) * 64;       // warp n offset (t)
    const int g = lane >> 2, q = lane & 3;

    const int b   = blockIdx.z;
    const int co0 = blockIdx.y * 128;
    const int tg0 = blockIdx.x * 128;

    const __half* wA = g_wA + (size_t)conv_sel * 3 * NC * NC;
    const size_t tbase = (size_t)b * TSTR * NC;

    // ldmatrix per-lane address components
    const int rA   = wm + (lane & 7) + ((lane >> 3) & 1) * 8;   // A row (mi=0)
    const int kAof = (lane >> 4) * 16;                          // A k byte off
    const int rB0  = wn + ((lane >> 4) * 8) + (lane & 7);       // B row base (p=0,tap=0)
    const int kBof = ((lane >> 3) & 1) * 16;                    // B k byte off

    float acc[2][8][4] = {};

    // prologue: chunks 0 and 1
    cv_load(sb, wA, tbase, co0, tg0, 0, tid);
    CP_COMMIT();
    cv_load(sb + CV_BUF, wA, tbase, co0, tg0, 32, tid);
    CP_COMMIT();

    for (int chunk = 0; chunk < 16; chunk++) {
        if (chunk == 15) { CP_WAIT0(); } else { CP_WAIT1(); }
        __syncthreads();
        if (chunk < 14) {
            cv_load(sb + ((chunk + 2) % 3) * CV_BUF, wA, tbase, co0, tg0, (chunk + 2) * 32, tid);
            CP_COMMIT();
        }
        const uint32_t sbuf = sb + (chunk % 3) * CV_BUF;
        const uint32_t sbB = sbuf + CV_B_OFF;

#pragma unroll
        for (int tap = 0; tap < 3; tap++) {
#pragma unroll
            for (int k16 = 0; k16 < 2; k16++) {
                uint32_t a0[4], a1[4];
                const uint32_t aBase = sbuf + tap * CV_ATILE + rA * CV_ASTRIDE + k16 * 32 + kAof;
                ldsm4(a0, aBase);
                ldsm4(a1, aBase + 16 * CV_ASTRIDE);
                const uint32_t kB = (uint32_t)(k16 * 32 + kBof);
#pragma unroll
                for (int p = 0; p < 4; p++) {
                    uint32_t bh[4], bl[4];
                    const uint32_t bAddr = sbB + (rB0 + tap + p * 16) * CV_ASTRIDE + kB;
                    ldsm4(bh, bAddr);
                    ldsm4(bl, bAddr + CV_BTILE);
                    mma16816(acc[0][2 * p],     a0, bh);
                    mma16816(acc[0][2 * p],     a0, bl);
                    mma16816(acc[0][2 * p + 1], a0, bh + 2);
                    mma16816(acc[0][2 * p + 1], a0, bl + 2);
                    mma16816(acc[1][2 * p],     a1, bh);
                    mma16816(acc[1][2 * p],     a1, bl);
                    mma16816(acc[1][2 * p + 1], a1, bh + 2);
                    mma16816(acc[1][2 * p + 1], a1, bl + 2);
                }
            }
        }
    }

    // ---- epilogue ----
    const float inv = 0.70710678118654752f;
#pragma unroll
    for (int mi = 0; mi < 2; mi++) {
        const int co_a = co0 + wm + mi * 16 + g;
        const int co_b = co_a + 8;
        const float bva = bias[co_a];
        const float bvb = bias[co_b];
        const size_t ra = ((size_t)b * NC + co_a) * NT;
        const size_t rb = ((size_t)b * NC + co_b) * NT;
#pragma unroll
        for (int nj = 0; nj < 8; nj++) {
            const int t = tg0 + wn + nj * 8 + q * 2;
            float2 va = make_float2(acc[mi][nj][0] + bva, acc[mi][nj][1] + bva);
            float2 vb = make_float2(acc[mi][nj][2] + bvb, acc[mi][nj][3] + bvb);
            if (FINAL) {
                const float2 xa = *(const float2*)&xres[ra + t];
                const float2 xb = *(const float2*)&xres[rb + t];
                va.x = (va.x + xa.x) * inv; va.y = (va.y + xa.y) * inv;
                vb.x = (vb.x + xb.x) * inv; vb.y = (vb.y + xb.y) * inv;
                *(float2*)&outp[ra + t] = va;
                *(float2*)&outp[rb + t] = vb;
            } else {
                *(float2*)&g_y2[ra + t] = va;
                *(float2*)&g_y2[rb + t] = vb;
            }
        }
    }
}

// ---------------------------------------------------------------------------
// Launch
// ---------------------------------------------------------------------------
extern "C" void kernel_launch(void* const* d_in, const int* in_sizes, int n_in,
                              void* d_out, int out_size) {
    const float* x       = (const float*)d_in[0];
    const float* s       = (const float*)d_in[1];
    const int*   lengths = (const int*)  d_in[2];
    const float* fc1_w   = (const float*)d_in[3];
    const float* fc1_b   = (const float*)d_in[4];
    const float* alpha1  = (const float*)d_in[5];
    const float* conv1_w = (const float*)d_in[6];
    const float* conv1_b = (const float*)d_in[7];
    const float* fc2_w   = (const float*)d_in[8];
    const float* fc2_b   = (const float*)d_in[9];
    const float* alpha2  = (const float*)d_in[10];
    const float* conv2_w = (const float*)d_in[11];
    const float* conv2_b = (const float*)d_in[12];
    float* out = (float*)d_out;

    cudaFuncSetAttribute(conv_mma_kernel<false>,
                         cudaFuncAttributeMaxDynamicSharedMemorySize, CV_SMEM_TOTAL);
    cudaFuncSetAttribute(conv_mma_kernel<true>,
                         cudaFuncAttributeMaxDynamicSharedMemorySize, CV_SMEM_TOTAL);

    winsum_s_kernel<<<NB * NS, 256>>>(s);
    wprep_kernel<<<2048, 256>>>(conv1_w, conv2_w);

    dim3 agrid(NT / 64, NC / 64, NB);        // (32, 8, 16)
    dim3 cgrid(NT / 128, NC / 128, NB);      // (16, 4, 16)

    adawin_kernel<false><<<agrid, 256>>>(fc1_w, fc1_b, alpha1, x, lengths);
    conv_mma_kernel<false><<<cgrid, 256, CV_SMEM_TOTAL>>>(0, conv1_b, nullptr, nullptr);
    adawin_kernel<true><<<agrid, 256>>>(fc2_w, fc2_b, alpha2, x, lengths);
    conv_mma_kernel<true><<<cgrid, 256, CV_SMEM_TOTAL>>>(1, conv2_b, x, out);
}

// round 17
// speedup vs baseline: 1.8818x; 1.2086x over previous
#include <cuda_runtime.h>
#include <cuda_bf16.h>
#include <cuda_fp16.h>
#include <cstdint>
#include <math.h>

// Problem constants
#define NB 16
#define NC 512
#define NS 128
#define NT 2048
#define PADW 18    // W_LEN/2, W_LEN=37
#define TSTR 2050  // padded t rows for transposed conv input (1 zero row each end)

// ---------------------------------------------------------------------------
// Device scratch (no allocation allowed; zero-initialized at module load,
// pad rows of g_T* are never written so they stay zero -> implicit conv pad)
// ---------------------------------------------------------------------------
__device__ float g_ws[NB * NS * NT];                              // win_sum(s) fp32 [b][s][t]
__device__ __align__(16) __half g_ws_h[NB * NT * NS];             // win_sum(s) fp16 [b][t][s]
__device__ float g_y2[(size_t)NB * NC * NT];                      // conv1 fp32 out
__device__ __align__(16) __half g_Thi[(size_t)NB * TSTR * NC];    // conv in, transposed, hi (fp16)
__device__ __align__(16) __half g_Tlo[(size_t)NB * TSTR * NC];    // conv in, transposed, lo (fp16)
__device__ __align__(16) __half g_wA[(size_t)2 * 3 * NC * NC];    // conv weights [conv][tap][co][ci] fp16
__device__ __align__(16) __half g_wfc[2 * 1024 * NS];             // fc weights, permuted, fp16

// ---------------------------------------------------------------------------
// PTX helpers
// ---------------------------------------------------------------------------
__device__ __forceinline__ void mma16816(float* c, const uint32_t* a, const uint32_t* b) {
    asm volatile(
        "mma.sync.aligned.m16n8k16.row.col.f32.f16.f16.f32 "
        "{%0,%1,%2,%3}, {%4,%5,%6,%7}, {%8,%9}, {%0,%1,%2,%3};"
        : "+f"(c[0]), "+f"(c[1]), "+f"(c[2]), "+f"(c[3])
        : "r"(a[0]), "r"(a[1]), "r"(a[2]), "r"(a[3]), "r"(b[0]), "r"(b[1]));
}
__device__ __forceinline__ void ldsm4(uint32_t* r, uint32_t addr) {
    asm volatile("ldmatrix.sync.aligned.m8n8.x4.shared.b16 {%0,%1,%2,%3}, [%4];"
        : "=r"(r[0]), "=r"(r[1]), "=r"(r[2]), "=r"(r[3]) : "r"(addr));
}
__device__ __forceinline__ void cp_async16(uint32_t saddr, const void* gptr) {
    asm volatile("cp.async.cg.shared.global [%0], [%1], 16;" :: "r"(saddr), "l"(gptr));
}
#define CP_COMMIT() asm volatile("cp.async.commit_group;" ::: "memory")
#define CP_WAIT0()  asm volatile("cp.async.wait_group 0;" ::: "memory")
#define CP_WAIT1()  asm volatile("cp.async.wait_group 1;" ::: "memory")

__device__ __forceinline__ uint32_t smem_u32(const void* p) {
    uint32_t a;
    asm("{ .reg .u64 t; cvta.to.shared.u64 t, %1; cvt.u32.u64 %0, t; }" : "=r"(a) : "l"(p));
    return a;
}

// ---------------------------------------------------------------------------
// Kernel 1: sliding window sum of s over t (window 37)
// ---------------------------------------------------------------------------
__global__ void __launch_bounds__(256) winsum_s_kernel(const float* __restrict__ s) {
    __shared__ float sm[NT + 2 * PADW];
    const int row = blockIdx.x;
    const float* src = s + (size_t)row * NT;
    const int tid = threadIdx.x;
    for (int t = tid; t < NT; t += 256) sm[PADW + t] = src[t];
    if (tid < PADW) { sm[tid] = 0.0f; sm[PADW + NT + tid] = 0.0f; }
    __syncthreads();

    const int t0 = tid * 8;
    float sum = 0.0f;
#pragma unroll
    for (int k = 0; k < 37; k++) sum += sm[t0 + k];
    float* dst = g_ws + (size_t)row * NT + t0;
    dst[0] = sum;
#pragma unroll
    for (int j = 1; j < 8; j++) {
        sum += sm[t0 + j + 36] - sm[t0 + j - 1];
        dst[j] = sum;
    }
}

// ---------------------------------------------------------------------------
// Kernel 1c: transpose+convert win_sum -> g_ws_h[b][t][s] fp16
// ---------------------------------------------------------------------------
__global__ void __launch_bounds__(256) transpose_ws_kernel() {
    __shared__ float tile[32][33];
    const int b = blockIdx.z;
    const int s0 = blockIdx.y * 32;
    const int t0 = blockIdx.x * 32;
    const int tx = threadIdx.x & 31, ty = threadIdx.x >> 5;
#pragma unroll
    for (int i = ty; i < 32; i += 8)
        tile[i][tx] = g_ws[((size_t)b * NS + s0 + i) * NT + t0 + tx];
    __syncthreads();
#pragma unroll
    for (int i = ty; i < 32; i += 8)
        g_ws_h[((size_t)b * NT + t0 + i) * NS + s0 + tx] = __float2half(tile[tx][i]);
}

// ---------------------------------------------------------------------------
// Kernel 1b: rearrange conv weights -> g_wA[conv][tap][co][ci] fp16
// ---------------------------------------------------------------------------
__global__ void __launch_bounds__(256) wprep_kernel(const float* __restrict__ w1,
                                                    const float* __restrict__ w2) {
    const int idx = blockIdx.x * 256 + threadIdx.x;   // over 2*512*512
    const int conv = idx >> 18;
    const int rem = idx & 262143;
    const int co = rem >> 9, ci = rem & 511;
    const float* w = conv ? w2 : w1;
#pragma unroll
    for (int tap = 0; tap < 3; tap++) {
        const float v = w[(co * NC + ci) * 3 + tap];
        g_wA[((size_t)(conv * 3 + tap) * NC + co) * NC + ci] = __float2half(v);
    }
}

// ---------------------------------------------------------------------------
// Kernel 1d: fc weights -> g_wfc[stage][R][k] fp16, permuted so each 128-row
// block = [64 gamma rows | 64 beta rows] of one 64-channel group.
// ---------------------------------------------------------------------------
__global__ void __launch_bounds__(256) wfc_prep_kernel(const float* __restrict__ fc1_w,
                                                       const float* __restrict__ fc2_w) {
    const int idx = blockIdx.x * 256 + threadIdx.x;   // over 2*1024*128
    const int st = idx >> 17;
    const int rem = idx & 131071;
    const int R = rem >> 7, k = rem & 127;
    const int b8 = R >> 7, r = R & 127;
    const int c = b8 * 64 + (r & 63);
    const int srcrow = (r < 64) ? c : (512 + c);
    const float* w = st ? fc2_w : fc1_w;
    g_wfc[idx] = __float2half(w[srcrow * NS + k]);
}

// ---------------------------------------------------------------------------
// Kernel 2: adawin stage via HMMA fp16.
// CTA: 64 channels (gamma+beta) x 128 t.  A=[128 rows][K=128], B=[128 t][K=128].
// Single resident K tile; fp16 gamma/beta SMEM stage; y staged transposed then
// written to g_T*[b][t+1][c] as full rows.
// ---------------------------------------------------------------------------
#define AW_STRIDE 272                         // bytes per 128-fp16 row (+pad)
#define AW_A_OFF  0
#define AW_B_OFF  (128 * AW_STRIDE)           // 34816
#define AW_ST_OFF (2 * 128 * AW_STRIDE)       // 69632, fp16 stage [128][132]
#define AW_SMEM_TOTAL (AW_ST_OFF + 128 * 132 * 2)  // 103424
// y-stage overlays A region: yhi at 0, ylo at 16896 (each 128x66 fp16)

template<bool STAGE2>
__global__ void __launch_bounds__(256) adawin_mma_kernel(
    const float* __restrict__ fc_b, const float* __restrict__ alpha,
    const float* __restrict__ xin_p, const int* __restrict__ lengths)
{
    extern __shared__ char smem[];
    const uint32_t sb = smem_u32(smem);
    const int tid = threadIdx.x;
    const int lane = tid & 31, wid = tid >> 5;
    const int wm = (wid & 3) * 32;
    const int wn = (wid >> 2) * 64;
    const int g = lane >> 2, q = lane & 3;

    const int b  = blockIdx.z;
    const int cb = blockIdx.y;           // 64-channel group
    const int t0 = blockIdx.x * 128;

    // ---- load A and B (cp.async) ----
    const __half* wfc = g_wfc + ((STAGE2 ? 1 : 0) * 1024 + cb * 128) * NS;
    const __half* wsb = g_ws_h + ((size_t)b * NT + t0) * NS;
#pragma unroll
    for (int n = tid; n < 2048; n += 256) {
        const int row = n >> 4, c16 = n & 15;
        cp_async16(sb + AW_A_OFF + row * AW_STRIDE + c16 * 16, wfc + row * NS + c16 * 8);
        cp_async16(sb + AW_B_OFF + row * AW_STRIDE + c16 * 16, wsb + row * NS + c16 * 8);
    }
    CP_COMMIT();

    const int rA   = wm + (lane & 7) + ((lane >> 3) & 1) * 8;
    const int kAof = (lane >> 4) * 16;
    const int rB0  = wn + ((lane >> 4) * 8) + (lane & 7);
    const int kBof = ((lane >> 3) & 1) * 16;

    float acc[2][8][4] = {};

    CP_WAIT0();
    __syncthreads();

#pragma unroll
    for (int k16 = 0; k16 < 8; k16++) {
        uint32_t a0[4], a1[4];
        const uint32_t aBase = sb + AW_A_OFF + rA * AW_STRIDE + k16 * 32 + kAof;
        ldsm4(a0, aBase);
        ldsm4(a1, aBase + 16 * AW_STRIDE);
        const uint32_t kB = (uint32_t)(k16 * 32 + kBof);
#pragma unroll
        for (int p = 0; p < 4; p++) {
            uint32_t bh[4];
            ldsm4(bh, sb + AW_B_OFF + (rB0 + p * 16) * AW_STRIDE + kB);
            mma16816(acc[0][2 * p],     a0, bh);
            mma16816(acc[0][2 * p + 1], a0, bh + 2);
            mma16816(acc[1][2 * p],     a1, bh);
            mma16816(acc[1][2 * p + 1], a1, bh + 2);
        }
    }

    // ---- write gamma/beta to fp16 stage [row 0-63: gamma, 64-127: beta][132] ----
    __half* stg = (__half*)(smem + AW_ST_OFF);
#pragma unroll
    for (int mi = 0; mi < 2; mi++) {
        const int m = wm + mi * 16 + g;
#pragma unroll
        for (int nj = 0; nj < 8; nj++) {
            const int n = wn + nj * 8 + q * 2;
            *(__half2*)&stg[m * 132 + n]       = __floats2half2_rn(acc[mi][nj][0], acc[mi][nj][1]);
            *(__half2*)&stg[(m + 8) * 132 + n] = __floats2half2_rn(acc[mi][nj][2], acc[mi][nj][3]);
        }
    }
    __syncthreads();

    // ---- epilogue: y = lrelu((1+gamma)*tanh(alpha*x) + beta), staged transposed ----
    const int len = lengths[b];
    const float al = alpha[0];
    const float* xin = STAGE2 ? (const float*)g_y2 : xin_p;
    __half* yhi = (__half*)smem;            // [128 t][66], overlays A
    __half* ylo = (__half*)(smem + 16896);

#pragma unroll
    for (int i = 0; i < 32; i++) {
        const int idx = tid + i * 256;      // over 64c x 128t
        const int c_l = idx >> 7, t_l = idx & 127;
        const int c = cb * 64 + c_l;
        const int t = t0 + t_l;
        const float gamma = __half2float(stg[c_l * 132 + t_l]);
        const float beta  = __half2float(stg[(c_l + 64) * 132 + t_l]);
        const float bg = fc_b[c];
        const float bb = fc_b[c + 512];
        const int lo = max(t - PADW, 0);
        const int hi = min(t + PADW, NT - 1);
        const float nwin = (float)(hi - lo + 1);
        int cnt = min(hi, len - 1) - lo + 1;
        cnt = max(cnt, 0);
        const float denom = (float)cnt + 1e-9f;
        const float m = (t < len) ? 1.0f : 0.0f;
        const float gam = (gamma + bg * nwin) / denom * m;
        const float bet = (beta + bb * nwin) / denom * m;
        const float xn = tanhf(al * xin[((size_t)b * NC + c) * NT + t]);
        float v = (1.0f + gam) * xn + bet;
        v = (v > 0.0f) ? v : 0.2f * v;
        const __half h = __float2half(v);
        yhi[t_l * 66 + c_l] = h;
        ylo[t_l * 66 + c_l] = __float2half(v - __half2float(h));
    }
    __syncthreads();

    // ---- copy y-stage rows out (full 128B rows per t) ----
    const uint32_t* yhi32 = (const uint32_t*)yhi;
    const uint32_t* ylo32 = (const uint32_t*)ylo;
    uint32_t* dhi = (uint32_t*)g_Thi;
    uint32_t* dlo = (uint32_t*)g_Tlo;
#pragma unroll
    for (int i = 0; i < 16; i++) {
        const int n = tid + i * 256;        // over 128 rows x 32 words
        const int row = n >> 5, w = n & 31;
        const size_t d = ((size_t)b * TSTR + t0 + row + 1) * 256 + cb * 32 + w;
        dhi[d] = yhi32[row * 33 + w];
        dlo[d] = ylo32[row * 33 + w];
    }
}

// ---------------------------------------------------------------------------
// Kernel 3: conv1d k=3 via mma.sync fp16 (weights single, data hi/lo: 2 products).
// (unchanged from R16)
// ---------------------------------------------------------------------------
#define CV_ASTRIDE 80
#define CV_ATILE   (128 * CV_ASTRIDE)
#define CV_B_OFF   (3 * CV_ATILE)
#define CV_BTILE   (130 * CV_ASTRIDE)
#define CV_BUF     (CV_B_OFF + 2 * CV_BTILE)
#define CV_SMEM_TOTAL (3 * CV_BUF)

__device__ __forceinline__ void cv_load(uint32_t sbuf, const __half* __restrict__ wA,
                                        size_t tbase, int co0, int tg0, int k0, int tid) {
#pragma unroll
    for (int n = tid; n < 1536; n += 256) {
        const int ts = n >> 9, rem = n & 511;
        const int row = rem >> 2, c8 = rem & 3;
        cp_async16(sbuf + ts * CV_ATILE + row * CV_ASTRIDE + c8 * 16,
                   wA + ((size_t)ts * NC + co0 + row) * NC + k0 + c8 * 8);
    }
#pragma unroll
    for (int i = 0; i < 5; i++) {
        const int n = tid + i * 256;
        if (n < 1040) {
            const int spl = n / 520, rem = n % 520;
            const int row = rem >> 2, c8 = rem & 3;
            const __half* src = (spl ? g_Tlo : g_Thi) + tbase;
            cp_async16(sbuf + CV_B_OFF + spl * CV_BTILE + row * CV_ASTRIDE + c8 * 16,
                       src + (size_t)(tg0 + row) * NC + k0 + c8 * 8);
        }
    }
}

template<bool FINAL>
__global__ void __launch_bounds__(256) conv_mma_kernel(
    int conv_sel, const float* __restrict__ bias,
    const float* __restrict__ xres, float* __restrict__ outp)
{
    extern __shared__ char smem[];
    const uint32_t sb = smem_u32(smem);
    const int tid = threadIdx.x;
    const int lane = tid & 31, wid = tid >> 5;
    const int wm = (wid & 3) * 32;
    const int wn = (wid >> 2) * 64;
    const int g = lane >> 2, q = lane & 3;

    const int b   = blockIdx.z;
    const int co0 = blockIdx.y * 128;
    const int tg0 = blockIdx.x * 128;

    const __half* wA = g_wA + (size_t)conv_sel * 3 * NC * NC;
    const size_t tbase = (size_t)b * TSTR * NC;

    const int rA   = wm + (lane & 7) + ((lane >> 3) & 1) * 8;
    const int kAof = (lane >> 4) * 16;
    const int rB0  = wn + ((lane >> 4) * 8) + (lane & 7);
    const int kBof = ((lane >> 3) & 1) * 16;

    float acc[2][8][4] = {};

    cv_load(sb, wA, tbase, co0, tg0, 0, tid);
    CP_COMMIT();
    cv_load(sb + CV_BUF, wA, tbase, co0, tg0, 32, tid);
    CP_COMMIT();

    for (int chunk = 0; chunk < 16; chunk++) {
        if (chunk == 15) { CP_WAIT0(); } else { CP_WAIT1(); }
        __syncthreads();
        if (chunk < 14) {
            cv_load(sb + ((chunk + 2) % 3) * CV_BUF, wA, tbase, co0, tg0, (chunk + 2) * 32, tid);
            CP_COMMIT();
        }
        const uint32_t sbuf = sb + (chunk % 3) * CV_BUF;
        const uint32_t sbB = sbuf + CV_B_OFF;

#pragma unroll
        for (int tap = 0; tap < 3; tap++) {
#pragma unroll
            for (int k16 = 0; k16 < 2; k16++) {
                uint32_t a0[4], a1[4];
                const uint32_t aBase = sbuf + tap * CV_ATILE + rA * CV_ASTRIDE + k16 * 32 + kAof;
                ldsm4(a0, aBase);
                ldsm4(a1, aBase + 16 * CV_ASTRIDE);
                const uint32_t kB = (uint32_t)(k16 * 32 + kBof);
#pragma unroll
                for (int p = 0; p < 4; p++) {
                    uint32_t bh[4], bl[4];
                    const uint32_t bAddr = sbB + (rB0 + tap + p * 16) * CV_ASTRIDE + kB;
                    ldsm4(bh, bAddr);
                    ldsm4(bl, bAddr + CV_BTILE);
                    mma16816(acc[0][2 * p],     a0, bh);
                    mma16816(acc[0][2 * p],     a0, bl);
                    mma16816(acc[0][2 * p + 1], a0, bh + 2);
                    mma16816(acc[0][2 * p + 1], a0, bl + 2);
                    mma16816(acc[1][2 * p],     a1, bh);
                    mma16816(acc[1][2 * p],     a1, bl);
                    mma16816(acc[1][2 * p + 1], a1, bh + 2);
                    mma16816(acc[1][2 * p + 1], a1, bl + 2);
                }
            }
        }
    }

    const float inv = 0.70710678118654752f;
#pragma unroll
    for (int mi = 0; mi < 2; mi++) {
        const int co_a = co0 + wm + mi * 16 + g;
        const int co_b = co_a + 8;
        const float bva = bias[co_a];
        const float bvb = bias[co_b];
        const size_t ra = ((size_t)b * NC + co_a) * NT;
        const size_t rb = ((size_t)b * NC + co_b) * NT;
#pragma unroll
        for (int nj = 0; nj < 8; nj++) {
            const int t = tg0 + wn + nj * 8 + q * 2;
            float2 va = make_float2(acc[mi][nj][0] + bva, acc[mi][nj][1] + bva);
            float2 vb = make_float2(acc[mi][nj][2] + bvb, acc[mi][nj][3] + bvb);
            if (FINAL) {
                const float2 xa = *(const float2*)&xres[ra + t];
                const float2 xb = *(const float2*)&xres[rb + t];
                va.x = (va.x + xa.x) * inv; va.y = (va.y + xa.y) * inv;
                vb.x = (vb.x + xb.x) * inv; vb.y = (vb.y + xb.y) * inv;
                *(float2*)&outp[ra + t] = va;
                *(float2*)&outp[rb + t] = vb;
            } else {
                *(float2*)&g_y2[ra + t] = va;
                *(float2*)&g_y2[rb + t] = vb;
            }
        }
    }
}

// ---------------------------------------------------------------------------
// Launch
// ---------------------------------------------------------------------------
extern "C" void kernel_launch(void* const* d_in, const int* in_sizes, int n_in,
                              void* d_out, int out_size) {
    const float* x       = (const float*)d_in[0];
    const float* s       = (const float*)d_in[1];
    const int*   lengths = (const int*)  d_in[2];
    const float* fc1_w   = (const float*)d_in[3];
    const float* fc1_b   = (const float*)d_in[4];
    const float* alpha1  = (const float*)d_in[5];
    const float* conv1_w = (const float*)d_in[6];
    const float* conv1_b = (const float*)d_in[7];
    const float* fc2_w   = (const float*)d_in[8];
    const float* fc2_b   = (const float*)d_in[9];
    const float* alpha2  = (const float*)d_in[10];
    const float* conv2_w = (const float*)d_in[11];
    const float* conv2_b = (const float*)d_in[12];
    float* out = (float*)d_out;

    cudaFuncSetAttribute(conv_mma_kernel<false>,
                         cudaFuncAttributeMaxDynamicSharedMemorySize, CV_SMEM_TOTAL);
    cudaFuncSetAttribute(conv_mma_kernel<true>,
                         cudaFuncAttributeMaxDynamicSharedMemorySize, CV_SMEM_TOTAL);
    cudaFuncSetAttribute(adawin_mma_kernel<false>,
                         cudaFuncAttributeMaxDynamicSharedMemorySize, AW_SMEM_TOTAL);
    cudaFuncSetAttribute(adawin_mma_kernel<true>,
                         cudaFuncAttributeMaxDynamicSharedMemorySize, AW_SMEM_TOTAL);

    winsum_s_kernel<<<NB * NS, 256>>>(s);
    wprep_kernel<<<2048, 256>>>(conv1_w, conv2_w);
    wfc_prep_kernel<<<1024, 256>>>(fc1_w, fc2_w);
    {
        dim3 tgrid(NT / 32, NS / 32, NB);    // (64, 4, 16)
        transpose_ws_kernel<<<tgrid, 256>>>();
    }

    dim3 awgrid(NT / 128, NC / 64, NB);      // (16, 8, 16)
    dim3 cgrid(NT / 128, NC / 128, NB);      // (16, 4, 16)

    adawin_mma_kernel<false><<<awgrid, 256, AW_SMEM_TOTAL>>>(fc1_b, alpha1, x, lengths);
    conv_mma_kernel<false><<<cgrid, 256, CV_SMEM_TOTAL>>>(0, conv1_b, nullptr, nullptr);
    adawin_mma_kernel<true><<<awgrid, 256, AW_SMEM_TOTAL>>>(fc2_b, alpha2, x, lengths);
    conv_mma_kernel<true><<<cgrid, 256, CV_SMEM_TOTAL>>>(1, conv2_b, x, out);
}